// round 1
// baseline (speedup 1.0000x reference)
#include <cuda_runtime.h>

// QSP expectation kernel:
//   state row (p0,p1) complex, init (1,0)
//   per step k (phi = phis[k+1]):
//     u = p0*C + i*S*p1 ; v = i*S*p0 + p1*C        (W(theta) rotation)
//     p0 = u * e^{i phi} ; p1 = v * e^{-i phi}     (S(phi) rotation)
//   out = alpha * Re( e^{i phi0} * p0 ) + bias
//
// Packed f32x2: each thread carries TWO independent elements (lane-pair),
// all 54 steps fully unrolled, phase constants broadcast from shared memory.

#define NSTEP 54   // 2*QSP_DEPTH with DEPTH=27 -> 55 phases, 54 matrix steps

typedef unsigned long long u64;

__device__ __forceinline__ u64 pk2(float lo, float hi) {
    u64 r;
    asm("mov.b64 %0, {%1, %2};" : "=l"(r) : "f"(lo), "f"(hi));
    return r;
}
__device__ __forceinline__ void upk2(u64 v, float& lo, float& hi) {
    asm("mov.b64 {%0, %1}, %2;" : "=f"(lo), "=f"(hi) : "l"(v));
}
__device__ __forceinline__ u64 fma2(u64 a, u64 b, u64 c) {
    u64 d;
    asm("fma.rn.f32x2 %0, %1, %2, %3;" : "=l"(d) : "l"(a), "l"(b), "l"(c));
    return d;
}
__device__ __forceinline__ u64 mul2(u64 a, u64 b) {
    u64 d;
    asm("mul.rn.f32x2 %0, %1, %2;" : "=l"(d) : "l"(a), "l"(b));
    return d;
}

template <int STEPS_CT>
__global__ void __launch_bounds__(256)
qsp_kernel(const float* __restrict__ x,
           const float* __restrict__ phis,
           const float* __restrict__ alphas,
           const float* __restrict__ bias,
           float* __restrict__ out,
           int n, int nsteps_rt)
{
    const int nsteps = (STEPS_CT > 0) ? STEPS_CT : nsteps_rt;

    // Phase constants, pre-packed for broadcast f32x2 use.
    __shared__ u64 sEC[256], sES[256], sNES[256];
    __shared__ float s0c, s0s;

    int t = threadIdx.x;
    if (t < nsteps) {
        float sp, cp;
        sincosf(phis[t + 1], &sp, &cp);
        sEC[t]  = pk2(cp, cp);
        sES[t]  = pk2(sp, sp);
        sNES[t] = pk2(-sp, -sp);
    }
    if (t == 0) {
        float sp, cp;
        sincosf(phis[0], &sp, &cp);
        s0c = cp; s0s = sp;
    }
    __syncthreads();

    const int half = n >> 1;
    const int i = blockIdx.x * blockDim.x + t;
    if (i >= half) return;
    const int j = i + half;

    float sa, ca, sb, cb;
    sincosf(x[i], &sa, &ca);
    sincosf(x[j], &sb, &cb);

    const u64 C2  = pk2(ca, cb);
    const u64 S2  = pk2(sa, sb);
    const u64 NS2 = pk2(-sa, -sb);

    u64 X0 = pk2(1.0f, 1.0f);   // Re(p0) lanes
    u64 Y0 = 0ull;              // Im(p0)
    u64 X1 = 0ull;              // Re(p1)
    u64 Y1 = 0ull;              // Im(p1)

    #pragma unroll
    for (int k = 0; k < nsteps; ++k) {
        const u64 EC  = sEC[k];
        const u64 ES  = sES[k];
        const u64 NES = sNES[k];

        // W(theta) rotation: u = p0*C + i*S*p1, v = i*S*p0 + p1*C
        const u64 ux = fma2(C2, X0, mul2(NS2, Y1));   // C*x0 - S*y1
        const u64 uy = fma2(C2, Y0, mul2(S2,  X1));   // C*y0 + S*x1
        const u64 vx = fma2(C2, X1, mul2(NS2, Y0));   // C*x1 - S*y0
        const u64 vy = fma2(C2, Y1, mul2(S2,  X0));   // C*y1 + S*x0

        // phase rotation: p0 = u*e^{i phi}, p1 = v*e^{-i phi}
        X0 = fma2(EC,  ux, mul2(NES, uy));   // ec*ux - es*uy
        Y0 = fma2(ES,  ux, mul2(EC,  uy));   // es*ux + ec*uy
        X1 = fma2(EC,  vx, mul2(ES,  vy));   // ec*vx + es*vy
        Y1 = fma2(NES, vx, mul2(EC,  vy));   // -es*vx + ec*vy
    }

    float x0a, x0b, y0a, y0b;
    upk2(X0, x0a, x0b);
    upk2(Y0, y0a, y0b);

    const float ec0 = s0c, es0 = s0s;
    const float b0  = bias[0];

    // Re( e^{i phi0} * p0 ) = ec0*x0 - es0*y0
    const float rea = fmaf(ec0, x0a, -es0 * y0a);
    const float reb = fmaf(ec0, x0b, -es0 * y0b);

    out[i] = fmaf(alphas[i], rea, b0);
    out[j] = fmaf(alphas[j], reb, b0);
}

extern "C" void kernel_launch(void* const* d_in, const int* in_sizes, int n_in,
                              void* d_out, int out_size)
{
    const float* x      = (const float*)d_in[0];
    const float* phis   = (const float*)d_in[1];
    const float* alphas = (const float*)d_in[2];
    const float* bias   = (const float*)d_in[3];
    float* out = (float*)d_out;

    const int n      = in_sizes[0];          // 524288
    const int nph    = in_sizes[1];          // 55
    const int nsteps = nph - 1;              // 54

    const int half    = n >> 1;
    const int threads = 256;
    const int blocks  = (half + threads - 1) / threads;

    if (nsteps == NSTEP) {
        qsp_kernel<NSTEP><<<blocks, threads>>>(x, phis, alphas, bias, out, n, nsteps);
    } else {
        qsp_kernel<0><<<blocks, threads>>>(x, phis, alphas, bias, out, n, nsteps);
    }
}

// round 2
// speedup vs baseline: 1.6314x; 1.6314x over previous
#include <cuda_runtime.h>

// QSP expectation via exact Fourier reconstruction.
//
// The 54-step chain  P = prod_k [ W(theta) S(phi_k) ]  has entries that are
// homogeneous degree-54 polynomials in (cos theta, sin theta) with
// phase-dependent coefficients. Hence
//   g(theta) = Re( e^{i phi0} P00 ) = sum_{j=0..27} A_j cos(2 j theta) + B_j sin(2 j theta).
// Kernel 1 evaluates the chain at 64 samples theta_k = pi*k/64 and does an
// exact 64-point DFT (band limit 27 < 32) to recover A_j, B_j.
// Kernel 2 evaluates the 55-coefficient series per element with two Clenshaw
// recurrences (~112 scalar FMA/element vs 432 for the direct chain),
// f32x2-packed two elements per thread.

#define NSTEP 54            // 2*QSP_DEPTH, depth 27
#define NHARM 27            // NSTEP/2
#define NSAMP 64

typedef unsigned long long u64;

__device__ float g_coef[64];   // [0..27] = A_j, [32+1..32+27] = B_j

__device__ __forceinline__ u64 pk2(float lo, float hi) {
    u64 r;
    asm("mov.b64 %0, {%1, %2};" : "=l"(r) : "f"(lo), "f"(hi));
    return r;
}
__device__ __forceinline__ void upk2(u64 v, float& lo, float& hi) {
    asm("mov.b64 {%0, %1}, %2;" : "=f"(lo), "=f"(hi) : "l"(v));
}
__device__ __forceinline__ u64 fma2(u64 a, u64 b, u64 c) {
    u64 d;
    asm("fma.rn.f32x2 %0, %1, %2, %3;" : "=l"(d) : "l"(a), "l"(b), "l"(c));
    return d;
}
__device__ __forceinline__ u64 mul2(u64 a, u64 b) {
    u64 d;
    asm("mul.rn.f32x2 %0, %1, %2;" : "=l"(d) : "l"(a), "l"(b));
    return d;
}

// ---------------------------------------------------------------------------
// Kernel 1: sample the chain at 64 angles, DFT -> Fourier coefficients.
// ---------------------------------------------------------------------------
__global__ void qsp_precompute(const float* __restrict__ phis)
{
    __shared__ float gsamp[NSAMP];
    __shared__ float pc[NSTEP], ps[NSTEP];

    const int t = threadIdx.x;   // 64 threads

    if (t < NSTEP) {
        float sp, cp;
        sincosf(phis[t + 1], &sp, &cp);
        pc[t] = cp; ps[t] = sp;
    }
    __syncthreads();

    // Evaluate chain at theta = pi * t / 64
    float s, c;
    sincospif((float)t * (1.0f / 64.0f), &s, &c);

    float x0 = 1.0f, y0 = 0.0f, x1 = 0.0f, y1 = 0.0f;
    #pragma unroll
    for (int k = 0; k < NSTEP; ++k) {
        const float ec = pc[k], es = ps[k];
        // W(theta): u = p0*c + i*s*p1 ; v = i*s*p0 + p1*c
        const float ux = c * x0 - s * y1;
        const float uy = c * y0 + s * x1;
        const float vx = c * x1 - s * y0;
        const float vy = c * y1 + s * x0;
        // phase: p0 = u*e^{i phi}, p1 = v*e^{-i phi}
        x0 = ec * ux - es * uy;
        y0 = es * ux + ec * uy;
        x1 = ec * vx + es * vy;
        y1 = ec * vy - es * vx;
    }

    float s0, c0;
    sincosf(phis[0], &s0, &c0);
    gsamp[t] = c0 * x0 - s0 * y0;      // g(theta_t)
    __syncthreads();

    // Exact 64-point DFT (harmonics 0..27 present only).
    if (t <= NHARM) {
        float acc = 0.0f;
        #pragma unroll 8
        for (int k = 0; k < NSAMP; ++k) {
            // cos(2*pi*t*k/64) = cospi( ((t*k) mod 64) / 32 )
            float cc = cospif((float)((t * k) & 63) * (1.0f / 32.0f));
            acc = fmaf(gsamp[k], cc, acc);
        }
        g_coef[t] = acc * ((t == 0) ? (1.0f / 64.0f) : (2.0f / 64.0f));
    } else if (t >= 32 && t - 31 <= NHARM) {
        const int j = t - 31;   // 1..27
        float acc = 0.0f;
        #pragma unroll 8
        for (int k = 0; k < NSAMP; ++k) {
            float ss = sinpif((float)((j * k) & 63) * (1.0f / 32.0f));
            acc = fmaf(gsamp[k], ss, acc);
        }
        g_coef[32 + j] = acc * (2.0f / 64.0f);
    }
}

// ---------------------------------------------------------------------------
// Kernel 2: per-element Fourier-series evaluation, two Clenshaw chains,
// f32x2-packed 2 elements per thread.
// ---------------------------------------------------------------------------
__global__ void __launch_bounds__(256)
qsp_eval(const float* __restrict__ x,
         const float* __restrict__ alphas,
         const float* __restrict__ bias,
         float* __restrict__ out,
         int n)
{
    __shared__ u64 sA[NHARM + 1], sB[NHARM + 1];
    __shared__ float sA0;

    const int t = threadIdx.x;
    if (t >= 1 && t <= NHARM) {
        float a = g_coef[t];
        sA[t] = pk2(a, a);
    }
    if (t == 0) sA0 = g_coef[0];
    if (t >= 32 && t - 31 <= NHARM) {
        const int j = t - 31;
        float b = g_coef[32 + j];
        sB[j] = pk2(b, b);
    }
    __syncthreads();

    const int half = n >> 1;
    const int i = blockIdx.x * blockDim.x + t;
    if (i >= half) return;
    const int j = i + half;

    // u = 2*theta
    float sa, ca, sb, cb;
    sincosf(2.0f * x[i], &sa, &ca);
    sincosf(2.0f * x[j], &sb, &cb);

    const u64 twox = pk2(2.0f * ca, 2.0f * cb);
    const u64 neg1 = pk2(-1.0f, -1.0f);

    u64 b1 = 0ull, b2 = 0ull;   // cos-series Clenshaw
    u64 d1 = 0ull, d2 = 0ull;   // sin-series Clenshaw

    #pragma unroll
    for (int k = NHARM; k >= 1; --k) {
        const u64 t1 = fma2(neg1, b2, sA[k]);   // A_k - b2
        const u64 nb = fma2(twox, b1, t1);      // 2x*b1 + (A_k - b2)
        b2 = b1; b1 = nb;
        const u64 t2 = fma2(neg1, d2, sB[k]);
        const u64 nd = fma2(twox, d1, t2);
        d2 = d1; d1 = nd;
    }

    // f = A0 + cos(u)*b1 - b2 + sin(u)*d1
    const u64 cu = pk2(ca, cb);
    const u64 su = pk2(sa, sb);
    u64 f = fma2(neg1, b2, pk2(sA0, sA0));
    f = fma2(cu, b1, f);
    f = fma2(su, d1, f);

    float fa, fb;
    upk2(f, fa, fb);

    const float b0 = bias[0];
    out[i] = fmaf(alphas[i], fa, b0);
    out[j] = fmaf(alphas[j], fb, b0);
}

// ---------------------------------------------------------------------------
// Fallback (round-1 kernel) for unexpected phase counts.
// ---------------------------------------------------------------------------
__global__ void __launch_bounds__(256)
qsp_generic(const float* __restrict__ x,
            const float* __restrict__ phis,
            const float* __restrict__ alphas,
            const float* __restrict__ bias,
            float* __restrict__ out,
            int n, int nsteps)
{
    __shared__ float pc[256], ps[256];
    __shared__ float s0c, s0s;
    int t = threadIdx.x;
    if (t < nsteps && t < 256) {
        float sp, cp;
        sincosf(phis[t + 1], &sp, &cp);
        pc[t] = cp; ps[t] = sp;
    }
    if (t == 0) {
        float sp, cp;
        sincosf(phis[0], &sp, &cp);
        s0c = cp; s0s = sp;
    }
    __syncthreads();

    const int i = blockIdx.x * blockDim.x + t;
    if (i >= n) return;

    float s, c;
    sincosf(x[i], &s, &c);
    float x0 = 1.0f, y0 = 0.0f, x1 = 0.0f, y1 = 0.0f;
    for (int k = 0; k < nsteps; ++k) {
        const float ec = (k < 256) ? pc[k] : cosf(phis[k + 1]);
        const float es = (k < 256) ? ps[k] : sinf(phis[k + 1]);
        const float ux = c * x0 - s * y1;
        const float uy = c * y0 + s * x1;
        const float vx = c * x1 - s * y0;
        const float vy = c * y1 + s * x0;
        x0 = ec * ux - es * uy;
        y0 = es * ux + ec * uy;
        x1 = ec * vx + es * vy;
        y1 = ec * vy - es * vx;
    }
    const float re = s0c * x0 - s0s * y0;
    out[i] = fmaf(alphas[i], re, bias[0]);
}

extern "C" void kernel_launch(void* const* d_in, const int* in_sizes, int n_in,
                              void* d_out, int out_size)
{
    const float* x      = (const float*)d_in[0];
    const float* phis   = (const float*)d_in[1];
    const float* alphas = (const float*)d_in[2];
    const float* bias   = (const float*)d_in[3];
    float* out = (float*)d_out;

    const int n      = in_sizes[0];
    const int nph    = in_sizes[1];
    const int nsteps = nph - 1;

    if (nsteps == NSTEP && (n & 1) == 0) {
        qsp_precompute<<<1, NSAMP>>>(phis);
        const int half    = n >> 1;
        const int threads = 256;
        const int blocks  = (half + threads - 1) / threads;
        qsp_eval<<<blocks, threads>>>(x, alphas, bias, out, n);
    } else {
        const int threads = 256;
        const int blocks  = (n + threads - 1) / threads;
        qsp_generic<<<blocks, threads>>>(x, phis, alphas, bias, out, n, nsteps);
    }
}